// round 3
// baseline (speedup 1.0000x reference)
#include <cuda_runtime.h>

#define N_SPARSE 16
#define N_VARLEN 4
#define SEQ_L 50
#define VOCAB 1000000
#define EPSV 1e-8f
#define ROW_LEN (N_SPARSE + N_VARLEN * SEQ_L)   // 216
#define OUT_LEN (N_SPARSE + N_VARLEN)           // 20
#define ROWS_PER_BLOCK 4
#define THREADS (ROWS_PER_BLOCK * 32)           // 128

__device__ __forceinline__ float warp_sum(float v) {
    #pragma unroll
    for (int o = 16; o; o >>= 1)
        v += __shfl_xor_sync(0xffffffffu, v, o);
    return v;
}

__global__ __launch_bounds__(THREADS) void emb_pool_kernel(
    const int* __restrict__ X,
    const float* __restrict__ sparse_tables,
    const float* __restrict__ varlen_tables,
    float* __restrict__ out)
{
    __shared__ int sx[ROWS_PER_BLOCK][ROW_LEN];

    const int tid  = threadIdx.x;
    const int base = blockIdx.x * ROWS_PER_BLOCK;

    // Vectorized, coalesced stage of 4 rows of X into shared memory.
    // ROWS_PER_BLOCK*ROW_LEN = 864 ints = 216 int4; block offset is 16B-aligned.
    {
        const int4* Xb4 = (const int4*)(X + (size_t)base * ROW_LEN);
        int4* sx4 = (int4*)&sx[0][0];
        #pragma unroll
        for (int i = tid; i < (ROWS_PER_BLOCK * ROW_LEN) / 4; i += THREADS)
            sx4[i] = Xb4[i];
    }
    __syncthreads();

    const int w    = tid >> 5;
    const int lane = tid & 31;
    const int row  = base + w;
    float* orow = out + (size_t)row * OUT_LEN;

    // ---- Sparse features: lanes 0..15 each do one gather ----
    float sparse_val = 0.f;
    if (lane < N_SPARSE) {
        int id = sx[w][lane];
        sparse_val = __ldg(sparse_tables + (size_t)lane * VOCAB + id);
    }

    // ---- Varlen features: issue all gathers, counts via ballot+popc ----
    float s[N_VARLEN];
    int   cnt[N_VARLEN];

    #pragma unroll
    for (int v = 0; v < N_VARLEN; v++) {
        const int* ids = &sx[w][N_SPARSE + v * SEQ_L];
        int id0 = ids[lane];
        bool p0 = (id0 != 0);
        float sv = 0.f;
        if (p0) sv = __ldg(varlen_tables + (size_t)v * VOCAB + id0);

        bool active1 = (lane < SEQ_L - 32);
        int id1 = active1 ? ids[32 + lane] : 0;
        bool p1 = active1 && (id1 != 0);
        if (p1) sv += __ldg(varlen_tables + (size_t)v * VOCAB + id1);

        unsigned b0 = __ballot_sync(0xffffffffu, p0);
        unsigned b1 = __ballot_sync(0xffffffffu, p1);
        cnt[v] = __popc(b0) + __popc(b1);
        s[v] = sv;
    }

    // Sum reductions (4 independent trees, pipelined)
    #pragma unroll
    for (int v = 0; v < N_VARLEN; v++)
        s[v] = warp_sum(s[v]);

    // ---- Single coalesced store: lanes 0..19 each write one output float ----
    float val;
    if (lane < N_SPARSE) {
        val = sparse_val;
    } else {
        float sv, cv;
        if      (lane == 16) { sv = s[0]; cv = (float)cnt[0]; }
        else if (lane == 17) { sv = s[1]; cv = (float)cnt[1]; }
        else if (lane == 18) { sv = s[2]; cv = (float)cnt[2]; }
        else                 { sv = s[3]; cv = (float)cnt[3]; }
        val = sv / (cv + EPSV);
    }
    if (lane < OUT_LEN)
        orow[lane] = val;
}

extern "C" void kernel_launch(void* const* d_in, const int* in_sizes, int n_in,
                              void* d_out, int out_size)
{
    const int*   X  = (const int*)d_in[0];
    const float* st = (const float*)d_in[1];
    const float* vt = (const float*)d_in[2];
    float* out = (float*)d_out;

    const int B = in_sizes[0] / ROW_LEN;    // 16384
    const int grid = B / ROWS_PER_BLOCK;    // 4096

    emb_pool_kernel<<<grid, THREADS>>>(X, st, vt, out);
}